// round 1
// baseline (speedup 1.0000x reference)
#include <cuda_runtime.h>

#define NN 116
#define NE 6670
#define HID 64
#define ENCD 122

// ---- device scratch (no allocations allowed) ----
__device__ __align__(16) float g_z1[NN * HID];   // x0 @ W1 per node
__device__ float g_d1[NE];                        // edge_attr . p1
__device__ float g_gE[NE * 5];                    // relu(edge_attr) @ We
__device__ float g_Wc[HID * 4];                   // W2 @ Wl
__device__ float g_dv[NN];                        // x1 . pe
__device__ float g_q[NN * 4];                     // x1 @ Wc
__device__ float g_S[NN * 5];                     // per-node sum of h
__device__ float g_D[NN];                         // per-node sum of d2

__device__ __forceinline__ int eix(int a, int b) {  // a < b, triu order
    return a * (231 - a) / 2 + (b - a - 1);
}

// ============================================================================
// K1: independent front work.
//  blocks [0,116): per-node  z1[j] = (enc[j] @ W_enc + b_enc) @ W1
//  blocks [116,169): per-edge d1[e], g[e] = relu(ea[e]) @ We
//  block 169: Wc = W2 @ Wl
// ============================================================================
__global__ void k1(const float* __restrict__ enc, const float* __restrict__ ea,
                   const float* __restrict__ W_enc, const float* __restrict__ b_enc,
                   const float* __restrict__ W1,
                   const float* __restrict__ p1, const float* __restrict__ We,
                   const float* __restrict__ W2, const float* __restrict__ Wl) {
    int bid = blockIdx.x, t = threadIdx.x;
    if (bid < NN) {
        __shared__ float encs[ENCD];
        __shared__ float x0s[HID];
        __shared__ float part[2][HID];
        int p = t >> 6, h = t & 63;
        int j = bid;
        if (t < ENCD) encs[t] = enc[j * ENCD + t];
        __syncthreads();
        float acc = (p == 0) ? b_enc[h] : 0.f;
        int k0 = p * 61;
        #pragma unroll 8
        for (int k = k0; k < k0 + 61; ++k) acc += encs[k] * W_enc[k * HID + h];
        part[p][h] = acc;
        __syncthreads();
        if (t < HID) x0s[t] = part[0][t] + part[1][t];
        __syncthreads();
        float az = 0.f;
        int m0 = p * 32;
        #pragma unroll
        for (int k = m0; k < m0 + 32; ++k) az += x0s[k] * W1[k * HID + h];
        part[p][h] = az;
        __syncthreads();
        if (t < HID) g_z1[j * HID + t] = part[0][t] + part[1][t];
    } else if (bid < NN + 53) {
        int e = (bid - NN) * 128 + t;
        if (e < NE) {
            float a[5], r[5];
            #pragma unroll
            for (int c = 0; c < 5; c++) { a[c] = ea[e * 5 + c]; r[c] = fmaxf(a[c], 0.f); }
            float d = 0.f;
            #pragma unroll
            for (int c = 0; c < 5; c++) d += a[c] * __ldg(&p1[c]);
            g_d1[e] = d;
            #pragma unroll
            for (int c2 = 0; c2 < 5; c2++) {
                float s = 0.f;
                #pragma unroll
                for (int c = 0; c < 5; c++) s += r[c] * __ldg(&We[c * 5 + c2]);
                g_gE[e * 5 + c2] = s;
            }
        }
    } else {
        for (int idx = t; idx < HID * 4; idx += 128) {
            int k = idx >> 2, o = idx & 3;
            float s = 0.f;
            #pragma unroll 8
            for (int h = 0; h < HID; h++) s += W2[k * HID + h] * Wl[h * 4 + o];
            g_Wc[idx] = s;
        }
    }
}

// ============================================================================
// K2: per node i:  x1[i,h] = relu(b1[h] + sum_{j!=i} d1[e(i,j)] * z1[j,h])
//     then dv[i] = x1[i] . pe ;  q[i,o] = x1[i] . Wc[:,o]
// ============================================================================
__global__ void k2(const float* __restrict__ b1, const float* __restrict__ pe) {
    __shared__ float z1s[NN * HID];
    __shared__ float d1s[NN];
    __shared__ float rp[2][HID];
    __shared__ float x1s[HID];
    __shared__ float red5[64][5];
    int i = blockIdx.x, t = threadIdx.x, p = t >> 6, h = t & 63;

    const float4* zg = (const float4*)g_z1;
    float4* zs = (float4*)z1s;
    for (int u = t; u < NN * HID / 4; u += 128) zs[u] = zg[u];
    if (t < 115) {
        int k = t + (t >= i);
        int a = min(i, k), b = max(i, k);
        d1s[t] = g_d1[eix(a, b)];
    }
    __syncthreads();

    float acc = p ? 0.f : b1[h];
    int u0 = p * 58, u1 = p ? 115 : 58;
    #pragma unroll 8
    for (int u = u0; u < u1; ++u) {
        int k = u + (u >= i);
        acc += d1s[u] * z1s[k * HID + h];
    }
    rp[p][h] = acc;
    __syncthreads();
    if (t < HID) x1s[t] = fmaxf(rp[0][t] + rp[1][t], 0.f);
    __syncthreads();

    if (t < HID) {
        float xv = x1s[t];
        #pragma unroll
        for (int o = 0; o < 4; o++) red5[t][o] = xv * g_Wc[t * 4 + o];
        red5[t][4] = xv * pe[t];
    }
    __syncthreads();
    for (int s = 32; s; s >>= 1) {
        if (t < s) {
            #pragma unroll
            for (int c = 0; c < 5; c++) red5[t][c] += red5[t + s][c];
        }
        __syncthreads();
    }
    if (t < 4) g_q[i * 4 + t] = red5[0][t];
    if (t == 4) g_dv[i] = red5[0][4];
}

// ============================================================================
// K3: per node i:  S[i,c] = sum_{f ∋ i} g[f,c] / (max(dv_i, dv_k, 0) + eps)
// ============================================================================
__global__ void k3() {
    int i = blockIdx.x, t = threadIdx.x;
    __shared__ float red[128][5];
    float acc[5] = {0.f, 0.f, 0.f, 0.f, 0.f};
    float dvi = g_dv[i];
    if (t < 115) {
        int k = t + (t >= i);
        int a = min(i, k), b = max(i, k);
        int e = eix(a, b);
        float inv = 1.f / (fmaxf(fmaxf(dvi, g_dv[k]), 0.f) + 1e-10f);
        #pragma unroll
        for (int c = 0; c < 5; c++) acc[c] = g_gE[e * 5 + c] * inv;
    }
    #pragma unroll
    for (int c = 0; c < 5; c++) red[t][c] = acc[c];
    __syncthreads();
    for (int s = 64; s; s >>= 1) {
        if (t < s) {
            #pragma unroll
            for (int c = 0; c < 5; c++) red[t][c] += red[t + s][c];
        }
        __syncthreads();
    }
    if (t < 5) g_S[i * 5 + t] = red[0][t];
}

// ============================================================================
// K4: per node j:  D[j] = sum_{k!=j} p2 . relu(dv_j(S_j - h_e) + dv_k(S_k - h_e) + be)
//     with h_e = g[e] / (max(dv_j, dv_k, 0) + eps),  e = e(j,k)
// ============================================================================
__global__ void k4(const float* __restrict__ be, const float* __restrict__ p2) {
    int j = blockIdx.x, t = threadIdx.x;
    __shared__ float Sj[5];
    __shared__ float red[128];
    if (t < 5) Sj[t] = g_S[j * 5 + t];
    __syncthreads();
    float dvj = g_dv[j];
    float part = 0.f;
    if (t < 115) {
        int k = t + (t >= j);
        int a = min(j, k), b = max(j, k);
        int e = eix(a, b);
        float dvk = g_dv[k];
        float inv = 1.f / (fmaxf(fmaxf(dvj, dvk), 0.f) + 1e-10f);
        #pragma unroll
        for (int c = 0; c < 5; c++) {
            float hh = g_gE[e * 5 + c] * inv;
            float v = dvj * (Sj[c] - hh) + dvk * (g_S[k * 5 + c] - hh) + __ldg(&be[c]);
            part += fmaxf(v, 0.f) * __ldg(&p2[c]);
        }
    }
    red[t] = part;
    __syncthreads();
    for (int s = 64; s; s >>= 1) {
        if (t < s) red[t] += red[t + s];
        __syncthreads();
    }
    if (t == 0) g_D[j] = red[0];
}

// ============================================================================
// K5: out[o] = (1/N) sum_j D[j] q[j,o]  +  sum_h b2[h] Wl[h,o]  +  bl[o]
// ============================================================================
__global__ void k5(const float* __restrict__ b2, const float* __restrict__ Wl,
                   const float* __restrict__ bl, float* __restrict__ out) {
    int t = threadIdx.x;
    __shared__ float red[128][4];
    float part[4] = {0.f, 0.f, 0.f, 0.f};
    if (t < NN) {
        float Dt = g_D[t] * (1.0f / (float)NN);
        #pragma unroll
        for (int o = 0; o < 4; o++) part[o] = Dt * g_q[t * 4 + o];
    }
    if (t < HID) {
        float b2t = b2[t];
        #pragma unroll
        for (int o = 0; o < 4; o++) part[o] += b2t * Wl[t * 4 + o];
    }
    #pragma unroll
    for (int o = 0; o < 4; o++) red[t][o] = part[o];
    __syncthreads();
    for (int s = 64; s; s >>= 1) {
        if (t < s) {
            #pragma unroll
            for (int o = 0; o < 4; o++) red[t][o] += red[t + s][o];
        }
        __syncthreads();
    }
    if (t < 4) out[t] = red[0][t] + bl[t];
}

extern "C" void kernel_launch(void* const* d_in, const int* in_sizes, int n_in,
                              void* d_out, int out_size) {
    const float* enc   = (const float*)d_in[0];
    const float* ea    = (const float*)d_in[1];
    // d_in[2] = edge_index (int32) — triu order, reproduced by closed form; unused.
    const float* W_enc = (const float*)d_in[3];
    const float* b_enc = (const float*)d_in[4];
    const float* W1    = (const float*)d_in[5];
    const float* b1    = (const float*)d_in[6];
    const float* p1    = (const float*)d_in[7];
    const float* We    = (const float*)d_in[8];
    const float* be    = (const float*)d_in[9];
    const float* pe    = (const float*)d_in[10];
    const float* W2    = (const float*)d_in[11];
    const float* b2    = (const float*)d_in[12];
    const float* p2    = (const float*)d_in[13];
    const float* Wl    = (const float*)d_in[14];
    const float* bl    = (const float*)d_in[15];
    float* out = (float*)d_out;

    k1<<<170, 128>>>(enc, ea, W_enc, b_enc, W1, p1, We, W2, Wl);
    k2<<<116, 128>>>(b1, pe);
    k3<<<116, 128>>>();
    k4<<<116, 128>>>(be, p2);
    k5<<<1, 128>>>(b2, Wl, bl, out);
}